// round 16
// baseline (speedup 1.0000x reference)
#include <cuda_runtime.h>
#include <cuda_fp16.h>
#include <math.h>

// Problem constants
#define Bsz 640
#define Dd 512
#define Ss 4
#define Tt 10
#define TBsz 64
#define Ll 30
#define KBsz 196
#define MKB (Bsz*KBsz)   // 125440
#define TS 40            // T*S
#define BD (Bsz*Dd)
#define NMB (MKB/128)    // 980 m-blocks

typedef __half hf;

// ---------------- scratch (static device globals; no allocations) ----------
__device__ float g_q0[BD];
__device__ float g_qall[Ss*BD];
__device__ float g_ch[Bsz*Ss*Dd];
__device__ float g_chkv[2][Bsz*Ss*Dd];       // [0]=chkey [1]=chval
__device__ float g_normed[Bsz*Ss*Dd];
__device__ float g_Amat[TBsz*TS*TS];
__device__ float g_att[Bsz*Ss*Dd];
__device__ hf    g_kp [(size_t)MKB*Dd];      // know_proj, fp16
__device__ hf    g_kp2[(size_t)MKB*Dd];      // kp2, fp16
__device__ hf    g_e1 [(size_t)MKB*Dd];      // e1, fp16
__device__ hf    g_kn [(size_t)MKB*Dd];      // knowledge, fp16
__device__ hf    g_wb[4][Dd*Dd];             // weights, fp16
__device__ hf    g_mp16[BD];                 // mp in fp16 (per-iter)
__device__ float g_s4[4*(size_t)MKB];        // score partials per N-slice
__device__ float g_read[BD];
__device__ float g_Wcat[2][2*Dd*Dd];         // [0]=write_w copy, [1]=W2=write_w@mproj_w
__device__ float g_biascat[2][Dd];           // [0]=write_b copy, [1]=bias2
__device__ float g_Wkv[2][Dd*Dd];            // [0]=kq_w [1]=val_w (contiguous)
__device__ float g_bkv[2][Dd];
__device__ float g_zero[Dd];                 // stays zero (.bss)
__device__ float g_tmp512[Dd];
__device__ float g_zbuf[4*BD];               // [p][q][BD]: q=0 memory, q=1 mp
__device__ int   g_flags[NMB];               // producer/consumer handshake

__device__ __forceinline__ float eluf(float x){ return x > 0.f ? x : expm1f(x); }

__device__ __forceinline__ void mma_f16(float* cc, const unsigned* a, const unsigned* b){
    asm("mma.sync.aligned.m16n8k16.row.col.f32.f16.f16.f32 "
        "{%0,%1,%2,%3}, {%4,%5,%6,%7}, {%8,%9}, {%0,%1,%2,%3};"
        : "+f"(cc[0]), "+f"(cc[1]), "+f"(cc[2]), "+f"(cc[3])
        : "r"(a[0]), "r"(a[1]), "r"(a[2]), "r"(a[3]), "r"(b[0]), "r"(b[1]));
}
__device__ __forceinline__ void ldm4(unsigned* r, const hf* p){
    unsigned addr = (unsigned)__cvta_generic_to_shared(p);
    asm volatile("ldmatrix.sync.aligned.m8n8.x4.shared.b16 {%0,%1,%2,%3}, [%4];"
                 : "=r"(r[0]), "=r"(r[1]), "=r"(r[2]), "=r"(r[3]) : "r"(addr));
}
__device__ __forceinline__ void ldm4t(unsigned* r, const hf* p){
    unsigned addr = (unsigned)__cvta_generic_to_shared(p);
    asm volatile("ldmatrix.sync.aligned.m8n8.x4.trans.shared.b16 {%0,%1,%2,%3}, [%4];"
                 : "=r"(r[0]), "=r"(r[1]), "=r"(r[2]), "=r"(r[3]) : "r"(addr));
}
__device__ __forceinline__ void cpa16(void* sdst, const void* gsrc){
    unsigned s = (unsigned)__cvta_generic_to_shared(sdst);
    asm volatile("cp.async.cg.shared.global [%0], [%1], 16;" :: "r"(s), "l"(gsrc));
}
__device__ __forceinline__ void cpa_commit(){ asm volatile("cp.async.commit_group;"); }

// ----- shared tile geometry -----
#define TGK 512
#define TGN 512
#define TBK 32
#define NKIT (TGK/TBK)
#define NSTG 2
#define ALD 40
#define BLD 136
#define A_ST (128*ALD)
#define B_ST (TBK*BLD)
#define TG_SMEM (int)((NSTG*A_ST + NSTG*B_ST) * sizeof(hf))

// =============  prologue GEMM: fp16 single-pass, MODE4 only  =================
// C = fp16(acc + bias)
__global__ __launch_bounds__(256, 2)
void tgemm_k(const hf* __restrict__ Ag, const hf* __restrict__ Bg,
             const float* __restrict__ bias, hf* __restrict__ C)
{
    extern __shared__ hf smem[];
    hf* Abase = smem;
    hf* Bbase = smem + NSTG*A_ST;

    const int bm = blockIdx.y * 128;
    const int bn = blockIdx.x * 128;
    const int tid = threadIdx.x;
    const int wid = tid >> 5, lane = tid & 31;
    const int warp_m = wid & 1;
    const int warp_n = wid >> 1;
    const int r = lane >> 2, c = lane & 3;
    const int lrow = lane & 15, lcol = (lane >> 4) * 8;

    float acc[4][4][4];
    #pragma unroll
    for (int i = 0; i < 4; i++)
        #pragma unroll
        for (int j = 0; j < 4; j++)
            #pragma unroll
            for (int q = 0; q < 4; q++) acc[i][j][q] = 0.f;

    auto cpA = [&](int k0, int st){
        hf* As = Abase + st * A_ST;
        #pragma unroll
        for (int e2 = 0; e2 < 2; e2++) {
            int e   = tid * 2 + e2;
            int row = e >> 2;
            int seg = (e & 3) * 8;
            cpa16(As + row * ALD + seg,
                  Ag + (size_t)(bm + row) * TGK + k0 * TBK + seg);
        }
    };
    auto cpB = [&](int k0, int st){
        hf* Bs = Bbase + st * B_ST;
        #pragma unroll
        for (int e2 = 0; e2 < 2; e2++) {
            int e   = tid * 2 + e2;
            int row = e >> 4;
            int seg = (e & 15) * 8;
            cpa16(Bs + row * BLD + seg,
                  Bg + (size_t)(k0 * TBK + row) * TGN + bn + seg);
        }
        cpa_commit();
    };

    cpA(0, 0); cpB(0, 0);

    for (int k0 = 0; k0 < NKIT; k0++) {
        int st = k0 & 1;
        asm volatile("cp.async.wait_group 0;" ::: "memory");
        __syncthreads();
        if (k0 + 1 < NKIT) { cpA(k0 + 1, st ^ 1); cpB(k0 + 1, st ^ 1); }

        const hf* Ash = Abase + st * A_ST;
        const hf* Bsh = Bbase + st * B_ST;

        #pragma unroll
        for (int ks = 0; ks < 2; ks++) {
            unsigned ah[4][4], bh[4][2];
            int rr = ks * 16 + lrow;
            int cbase = warp_n * 32 + lcol;
            #pragma unroll
            for (int mt = 0; mt < 4; mt++) {
                int row = warp_m * 64 + mt * 16 + lrow;
                ldm4(ah[mt], Ash + row * ALD + ks * 16 + lcol);
            }
            #pragma unroll
            for (int p = 0; p < 2; p++) {
                unsigned t[4];
                ldm4t(t, Bsh + rr * BLD + cbase + p * 16);
                bh[2*p][0] = t[0]; bh[2*p][1] = t[1];
                bh[2*p+1][0] = t[2]; bh[2*p+1][1] = t[3];
            }
            #pragma unroll
            for (int mt = 0; mt < 4; mt++)
                #pragma unroll
                for (int nt = 0; nt < 4; nt++)
                    mma_f16(acc[mt][nt], ah[mt], bh[nt]);
        }
    }
    __syncthreads();

    #pragma unroll
    for (int mt = 0; mt < 4; mt++) {
        int m0 = bm + warp_m*64 + mt*16 + r;
        #pragma unroll
        for (int nt = 0; nt < 4; nt++) {
            int n0 = bn + warp_n*32 + nt*8 + 2*c;
            #pragma unroll
            for (int half = 0; half < 2; half++) {
                int mm = m0 + half*8;
                float vx = acc[mt][nt][2*half] + bias[n0];
                float vy = acc[mt][nt][2*half+1] + bias[n0+1];
                *(__half2*)(C + (size_t)mm*TGN + n0) =
                    __halves2half2(__float2half_rn(vx), __float2half_rn(vy));
            }
        }
    }
}

// ======  fused loop kernel: bx<4 -> e1 producer (scaled A), bx>=4 -> score ===
__global__ __launch_bounds__(256, 2)
void tg23_k(const hf* __restrict__ kp, const hf* __restrict__ W1,
            const hf* __restrict__ kp2, const hf* __restrict__ mp16,
            hf* __restrict__ e1,
            const hf* __restrict__ W3, const float* __restrict__ c2bias,
            const float* __restrict__ colmul, int cmStride,
            const float* __restrict__ rvec, float* __restrict__ svec,
            int* __restrict__ flags)
{
    extern __shared__ hf smem[];
    hf* Abase = smem;
    hf* Bbase = smem + NSTG*A_ST;

    const int by = blockIdx.y;
    const int bx = blockIdx.x;
    const bool isT2 = (bx < 4);
    const int bm = by * 128;
    const int bn = (isT2 ? bx : bx - 4) * 128;
    const int tid = threadIdx.x;
    const int wid = tid >> 5, lane = tid & 31;
    const int warp_m = wid & 1;
    const int warp_n = wid >> 1;
    const int r = lane >> 2, c = lane & 3;
    const int lrow = lane & 15, lcol = (lane >> 4) * 8;

    float acc[4][4][4];
    #pragma unroll
    for (int i = 0; i < 4; i++)
        #pragma unroll
        for (int j = 0; j < 4; j++)
            #pragma unroll
            for (int q = 0; q < 4; q++) acc[i][j][q] = 0.f;

    if (isT2) {
        // ---- producer: A = kp * mp16[b] (fused scale), B = W1 ----
        auto cpB = [&](int k0, int st){
            hf* Bs = Bbase + st * B_ST;
            #pragma unroll
            for (int e2 = 0; e2 < 2; e2++) {
                int e   = tid * 2 + e2;
                int row = e >> 4;
                int seg = (e & 15) * 8;
                cpa16(Bs + row * BLD + seg,
                      W1 + (size_t)(k0 * TBK + row) * TGN + bn + seg);
            }
            cpa_commit();
        };
        uint4 ka[2], ra[2];
        auto ldgA = [&](int kt){
            #pragma unroll
            for (int e2 = 0; e2 < 2; e2++) {
                int e   = tid * 2 + e2;
                int row = e >> 2;
                int seg = (e & 3) * 8;
                int m   = bm + row;
                int b   = m / KBsz;
                ka[e2] = *(const uint4*)(kp   + (size_t)m * TGK + kt * TBK + seg);
                ra[e2] = *(const uint4*)(mp16 + (size_t)b * TGK + kt * TBK + seg);
            }
        };
        auto stsA = [&](int st){
            hf* As = Abase + st * A_ST;
            #pragma unroll
            for (int e2 = 0; e2 < 2; e2++) {
                int e   = tid * 2 + e2;
                int row = e >> 2;
                int seg = (e & 3) * 8;
                const __half2* kk = (const __half2*)&ka[e2];
                const __half2* rr2 = (const __half2*)&ra[e2];
                uint4 outv;
                __half2* po = (__half2*)&outv;
                #pragma unroll
                for (int q = 0; q < 4; q++) po[q] = __hmul2(kk[q], rr2[q]);
                *(uint4*)(As + row * ALD + seg) = outv;
            }
        };

        ldgA(0); stsA(0); cpB(0, 0); ldgA(1);

        for (int k0 = 0; k0 < NKIT; k0++) {
            int st = k0 & 1;
            asm volatile("cp.async.wait_group 0;" ::: "memory");
            __syncthreads();
            if (k0 + 1 < NKIT) { stsA(st ^ 1); cpB(k0 + 1, st ^ 1); }
            if (k0 + 2 < NKIT) ldgA(k0 + 2);

            const hf* Ash = Abase + st * A_ST;
            const hf* Bsh = Bbase + st * B_ST;

            #pragma unroll
            for (int ks = 0; ks < 2; ks++) {
                unsigned ah[4][4], bh[4][2];
                int rr = ks * 16 + lrow;
                int cbase = warp_n * 32 + lcol;
                #pragma unroll
                for (int mt = 0; mt < 4; mt++) {
                    int row = warp_m * 64 + mt * 16 + lrow;
                    ldm4(ah[mt], Ash + row * ALD + ks * 16 + lcol);
                }
                #pragma unroll
                for (int p = 0; p < 2; p++) {
                    unsigned t[4];
                    ldm4t(t, Bsh + rr * BLD + cbase + p * 16);
                    bh[2*p][0] = t[0]; bh[2*p][1] = t[1];
                    bh[2*p+1][0] = t[2]; bh[2*p+1][1] = t[3];
                }
                #pragma unroll
                for (int mt = 0; mt < 4; mt++)
                    #pragma unroll
                    for (int nt = 0; nt < 4; nt++)
                        mma_f16(acc[mt][nt], ah[mt], bh[nt]);
            }
        }
        __syncthreads();

        // epilogue: e1 = fp16(elu(acc + kp2))
        #pragma unroll
        for (int mt = 0; mt < 4; mt++) {
            int m0 = bm + warp_m*64 + mt*16 + r;
            #pragma unroll
            for (int nt = 0; nt < 4; nt++) {
                int n0 = bn + warp_n*32 + nt*8 + 2*c;
                #pragma unroll
                for (int half = 0; half < 2; half++) {
                    int mm = m0 + half*8;
                    size_t gm = (size_t)mm*TGN + n0;
                    __half2 ad = *(const __half2*)(kp2 + gm);
                    float vx = eluf(acc[mt][nt][2*half]   + __half2float(__low2half(ad)));
                    float vy = eluf(acc[mt][nt][2*half+1] + __half2float(__high2half(ad)));
                    *(__half2*)(e1 + gm) =
                        __halves2half2(__float2half_rn(vx), __float2half_rn(vy));
                }
            }
        }
        __syncthreads();
        if (tid == 0) {
            __threadfence();
            atomicAdd(&flags[by], 1);
        }
    } else {
        // ---- consumer: wait for the 4 producer slices of this row block ----
        if (tid == 0) {
            while (((volatile int*)flags)[by] < 4) { }
            __threadfence();
        }
        __syncthreads();

        auto cpA = [&](int k0, int st){
            hf* As = Abase + st * A_ST;
            #pragma unroll
            for (int e2 = 0; e2 < 2; e2++) {
                int e   = tid * 2 + e2;
                int row = e >> 2;
                int seg = (e & 3) * 8;
                cpa16(As + row * ALD + seg,
                      e1 + (size_t)(bm + row) * TGK + k0 * TBK + seg);
            }
        };
        auto cpB = [&](int k0, int st){
            hf* Bs = Bbase + st * B_ST;
            #pragma unroll
            for (int e2 = 0; e2 < 2; e2++) {
                int e   = tid * 2 + e2;
                int row = e >> 4;
                int seg = (e & 15) * 8;
                cpa16(Bs + row * BLD + seg,
                      W3 + (size_t)(k0 * TBK + row) * TGN + bn + seg);
            }
            cpa_commit();
        };

        cpA(0, 0); cpB(0, 0);

        for (int k0 = 0; k0 < NKIT; k0++) {
            int st = k0 & 1;
            asm volatile("cp.async.wait_group 0;" ::: "memory");
            __syncthreads();
            if (k0 + 1 < NKIT) { cpA(k0 + 1, st ^ 1); cpB(k0 + 1, st ^ 1); }

            const hf* Ash = Abase + st * A_ST;
            const hf* Bsh = Bbase + st * B_ST;

            #pragma unroll
            for (int ks = 0; ks < 2; ks++) {
                unsigned ah[4][4], bh[4][2];
                int rr = ks * 16 + lrow;
                int cbase = warp_n * 32 + lcol;
                #pragma unroll
                for (int mt = 0; mt < 4; mt++) {
                    int row = warp_m * 64 + mt * 16 + lrow;
                    ldm4(ah[mt], Ash + row * ALD + ks * 16 + lcol);
                }
                #pragma unroll
                for (int p = 0; p < 2; p++) {
                    unsigned t[4];
                    ldm4t(t, Bsh + rr * BLD + cbase + p * 16);
                    bh[2*p][0] = t[0]; bh[2*p][1] = t[1];
                    bh[2*p+1][0] = t[2]; bh[2*p+1][1] = t[3];
                }
                #pragma unroll
                for (int mt = 0; mt < 4; mt++)
                    #pragma unroll
                    for (int nt = 0; nt < 4; nt++)
                        mma_f16(acc[mt][nt], ah[mt], bh[nt]);
            }
        }
        __syncthreads();

        __shared__ float sred[128];
        if (tid < 128) sred[tid] = 0.f;
        __syncthreads();
        #pragma unroll
        for (int mt = 0; mt < 4; mt++) {
            int mloc = warp_m*64 + mt*16 + r;
            int m0 = bm + mloc;
            int b0 = m0 / KBsz;
            int b1 = (m0 + 8) / KBsz;
            float p0 = 0.f, p1 = 0.f;
            #pragma unroll
            for (int nt = 0; nt < 4; nt++) {
                int n0 = bn + warp_n*32 + nt*8 + 2*c;
                float v;
                v = eluf((acc[mt][nt][0] + c2bias[n0  ]) * colmul[(size_t)b0*cmStride + n0  ]); p0 += v*rvec[n0];
                v = eluf((acc[mt][nt][1] + c2bias[n0+1]) * colmul[(size_t)b0*cmStride + n0+1]); p0 += v*rvec[n0+1];
                v = eluf((acc[mt][nt][2] + c2bias[n0  ]) * colmul[(size_t)b1*cmStride + n0  ]); p1 += v*rvec[n0];
                v = eluf((acc[mt][nt][3] + c2bias[n0+1]) * colmul[(size_t)b1*cmStride + n0+1]); p1 += v*rvec[n0+1];
            }
            p0 += __shfl_xor_sync(0xffffffffu, p0, 1);
            p0 += __shfl_xor_sync(0xffffffffu, p0, 2);
            p1 += __shfl_xor_sync(0xffffffffu, p1, 1);
            p1 += __shfl_xor_sync(0xffffffffu, p1, 2);
            if (c == 0) { atomicAdd(&sred[mloc], p0); atomicAdd(&sred[mloc + 8], p1); }
        }
        __syncthreads();
        if (tid < 128)
            svec[(size_t)(bx - 4) * MKB + bm + tid] = sred[tid];
    }
}

// ---------------- helper kernels ---------------------------------------------
__global__ void cvt16_k(const float* __restrict__ src, hf* __restrict__ dst, size_t n)
{
    size_t i = ((size_t)blockIdx.x * blockDim.x + threadIdx.x) * 4;
    if (i >= n) return;
    float4 v = *(const float4*)(src + i);
    *(__half2*)(dst + i)     = __halves2half2(__float2half_rn(v.x), __float2half_rn(v.y));
    *(__half2*)(dst + i + 2) = __halves2half2(__float2half_rn(v.z), __float2half_rn(v.w));
}

__global__ void vecmat_k(const float* __restrict__ vec,
                         const float* __restrict__ W,
                         const float* __restrict__ b,
                         float* __restrict__ r)
{
    int n = blockIdx.x * blockDim.x + threadIdx.x;
    if (n >= Dd) return;
    float a = b[n];
    for (int k = 0; k < Dd; k++) a += vec[k] * W[(size_t)k * Dd + n];
    r[n] = a;
}

__global__ void copyf_k(const float* __restrict__ src, float* __restrict__ dst, int n)
{
    int i = (blockIdx.x * blockDim.x + threadIdx.x) * 4;
    if (i < n) *(float4*)(dst + i) = *(const float4*)(src + i);
}

__global__ void zerofl_k(int* __restrict__ f)
{
    int i = blockIdx.x * blockDim.x + threadIdx.x;
    if (i < NMB) f[i] = 0;
}

// =====================  small FFMA2 GEMM (64x128 tile)  ======================
__device__ __forceinline__ unsigned long long pack2(float lo, float hi) {
    unsigned long long r;
    asm("mov.b64 %0, {%1, %2};" : "=l"(r) : "f"(lo), "f"(hi));
    return r;
}
__device__ __forceinline__ void unpack2(unsigned long long v, float& lo, float& hi) {
    asm("mov.b64 {%0, %1}, %2;" : "=f"(lo), "=f"(hi) : "l"(v));
}
__device__ __forceinline__ void fma2(unsigned long long& d,
                                     unsigned long long a, unsigned long long b) {
    asm("fma.rn.f32x2 %0, %1, %2, %0;" : "+l"(d) : "l"(a), "l"(b));
}

#define SBM 64
#define SBN 128
#define BKK 16

// z-batched; optional fp16 mirror (written only when blockIdx.z == 1)
template<int MODE>
__global__ __launch_bounds__(256)
void sgemm_k(const float* __restrict__ A, int lda,
             const float* __restrict__ A2, int lda2, int splitK,
             const float* __restrict__ W,
             const float* __restrict__ bias,
             float* __restrict__ C,
             int M, int K, int N,
             size_t strideA, size_t strideW, size_t strideBias, size_t strideC,
             hf* __restrict__ C16)
{
    A    += (size_t)blockIdx.z * strideA;
    A2   += (size_t)blockIdx.z * strideA;
    W    += (size_t)blockIdx.z * strideW;
    bias += (size_t)blockIdx.z * strideBias;
    C    += (size_t)blockIdx.z * strideC;

    __shared__ float As[BKK][SBM];
    __shared__ float Bs[BKK][SBN];

    const int bm = blockIdx.y * SBM;
    const int bn = blockIdx.x * SBN;
    const int tid = threadIdx.x;
    const int ty = tid >> 5;
    const int tx = tid & 31;

    unsigned long long acc2[8][2];
    #pragma unroll
    for (int i = 0; i < 8; i++) { acc2[i][0] = 0ull; acc2[i][1] = 0ull; }

    for (int k0 = 0; k0 < K; k0 += BKK) {
        {
            int e   = tid;
            int row = e >> 2;
            int kq  = (e & 3) * 4;
            int m   = bm + row;
            int k   = k0 + kq;
            const float* src = (k < splitK)
                ? (A  + (size_t)m * lda  + k)
                : (A2 + (size_t)m * lda2 + (k - splitK));
            float4 v = *(const float4*)src;
            As[kq + 0][row] = v.x; As[kq + 1][row] = v.y;
            As[kq + 2][row] = v.z; As[kq + 3][row] = v.w;
        }
        #pragma unroll
        for (int e2 = 0; e2 < 2; e2++) {
            int e   = tid * 2 + e2;
            int row = e >> 5;
            int cc  = (e & 31) * 4;
            float4 v = *(const float4*)(W + (size_t)(k0 + row) * N + bn + cc);
            *(float4*)&Bs[row][cc] = v;
        }
        __syncthreads();
        #pragma unroll
        for (int kk = 0; kk < BKK; kk++) {
            float a[8];
            unsigned long long b2[2];
            #pragma unroll
            for (int i = 0; i < 8; i++) a[i] = As[kk][ty * 8 + i];
            b2[0] = *(const unsigned long long*)&Bs[kk][tx * 4];
            b2[1] = *(const unsigned long long*)&Bs[kk][tx * 4 + 2];
            #pragma unroll
            for (int i = 0; i < 8; i++) {
                unsigned long long pa = pack2(a[i], a[i]);
                fma2(acc2[i][0], pa, b2[0]);
                fma2(acc2[i][1], pa, b2[1]);
            }
        }
        __syncthreads();
    }

    #pragma unroll
    for (int i = 0; i < 8; i++) {
        int m = bm + ty * 8 + i;
        int n = bn + tx * 4;
        float4 v;
        unpack2(acc2[i][0], v.x, v.y);
        unpack2(acc2[i][1], v.z, v.w);
        v.x += bias[n]; v.y += bias[n+1]; v.z += bias[n+2]; v.w += bias[n+3];
        if (MODE == 1) { v.x = tanhf(v.x); v.y = tanhf(v.y); v.z = tanhf(v.z); v.w = tanhf(v.w); }
        *(float4*)(C + (size_t)m * N + n) = v;
        if (C16 != nullptr && blockIdx.z == 1) {
            *(__half2*)(C16 + (size_t)m * N + n) =
                __halves2half2(__float2half_rn(v.x), __float2half_rn(v.y));
            *(__half2*)(C16 + (size_t)m * N + n + 2) =
                __halves2half2(__float2half_rn(v.z), __float2half_rn(v.w));
        }
    }
}

// ---------------- attention / misc kernels (validated) -----------------------
__global__ void word_attn_k(const float* __restrict__ qall,
                            const float* __restrict__ qword,
                            const float* __restrict__ caw,
                            float* __restrict__ ch)
{
    int b = blockIdx.x, s = blockIdx.y;
    __shared__ float qs[Dd];
    __shared__ float lg[Ll];
    int tid = threadIdx.x;
    for (int d = tid; d < Dd; d += 256)
        qs[d] = qall[((size_t)s * Bsz + b) * Dd + d] * caw[d];
    __syncthreads();
    int wid = tid >> 5, lane = tid & 31;
    for (int l = wid; l < Ll; l += 8) {
        const float* qw = qword + ((size_t)b * Ll + l) * Dd;
        float a = 0.f;
        for (int d = lane; d < Dd; d += 32) a += qs[d] * qw[d];
        #pragma unroll
        for (int o = 16; o; o >>= 1) a += __shfl_xor_sync(0xffffffffu, a, o);
        if (lane == 0) lg[l] = a;
    }
    __syncthreads();
    if (tid == 0) {
        float mx = -INFINITY;
        for (int l = 0; l < Ll; l++) mx = fmaxf(mx, lg[l]);
        float sm = 0.f;
        for (int l = 0; l < Ll; l++) { float e = expf(lg[l] - mx); lg[l] = e; sm += e; }
        float inv = 1.f / sm;
        for (int l = 0; l < Ll; l++) lg[l] *= inv;
    }
    __syncthreads();
    for (int d = tid; d < Dd; d += 256) {
        float a = 0.f;
        for (int l = 0; l < Ll; l++) a += lg[l] * qword[((size_t)b * Ll + l) * Dd + d];
        ch[((size_t)b * Ss + s) * Dd + d] = a;
    }
}

__global__ void norm_k(const float* __restrict__ chkey, float* __restrict__ normed)
{
    int i = blockIdx.x * blockDim.x + threadIdx.x;
    if (i >= BD) return;
    int b = i >> 9, d = i & 511;
    size_t base = (size_t)b * Ss * Dd + d;
    float ss = 0.f;
    #pragma unroll
    for (int s = 0; s < Ss; s++) { float v = chkey[base + s * Dd]; ss += v * v; }
    float inv = 1.f / sqrtf(ss);
    #pragma unroll
    for (int s = 0; s < Ss; s++) normed[base + s * Dd] = chkey[base + s * Dd] * inv;
}

__global__ void gram_k(const float* __restrict__ normed, float* __restrict__ Amat)
{
    int tb = blockIdx.x, i = blockIdx.y;
    __shared__ float Ki[Dd];
    __shared__ float lg[TS];
    int tid = threadIdx.x;
    int ti = i / Ss, si = i % Ss;
    size_t rowi = ((size_t)(ti * TBsz + tb) * Ss + si) * Dd;
    for (int d = tid; d < Dd; d += 256) Ki[d] = normed[rowi + d];
    __syncthreads();
    int wid = tid >> 5, lane = tid & 31;
    for (int j = wid; j < TS; j += 8) {
        float a;
        if (j > i) a = -1e30f;
        else {
            int tj = j / Ss, sj = j % Ss;
            size_t rowj = ((size_t)(tj * TBsz + tb) * Ss + sj) * Dd;
            a = 0.f;
            for (int d = lane; d < Dd; d += 32) a += Ki[d] * normed[rowj + d];
            #pragma unroll
            for (int o = 16; o; o >>= 1) a += __shfl_xor_sync(0xffffffffu, a, o);
        }
        if (lane == 0) lg[j] = a;
    }
    __syncthreads();
    if (tid == 0) {
        float mx = -INFINITY;
        for (int j = 0; j < TS; j++) mx = fmaxf(mx, lg[j]);
        float sm = 0.f;
        for (int j = 0; j < TS; j++) { float e = expf(lg[j] - mx); lg[j] = e; sm += e; }
        float inv = 1.f / sm;
        for (int j = 0; j < TS; j++) lg[j] *= inv;
    }
    __syncthreads();
    if (tid < TS) Amat[((size_t)tb * TS + i) * TS + tid] = lg[tid];
}

__global__ void attv_k(const float* __restrict__ Amat,
                       const float* __restrict__ chval,
                       float* __restrict__ att)
{
    int tb = blockIdx.x, i = blockIdx.y;
    __shared__ float aw[TS];
    int tid = threadIdx.x;
    if (tid < TS) aw[tid] = Amat[((size_t)tb * TS + i) * TS + tid];
    __syncthreads();
    int ti = i / Ss, si = i % Ss;
    for (int d = tid; d < Dd; d += 256) {
        float a = 0.f;
        for (int j = 0; j <= i; j++) {
            int tj = j / Ss, sj = j % Ss;
            a += aw[j] * chval[((size_t)(tj * TBsz + tb) * Ss + sj) * Dd + d];
        }
        att[((size_t)(ti * TBsz + tb) * Ss + si) * Dd + d] = a;
    }
}

__global__ void bcast_k(const float* __restrict__ src, float* __restrict__ dst)
{
    int i = blockIdx.x * blockDim.x + threadIdx.x;
    if (i < BD) dst[i] = src[i & 511];
}

__global__ void bcast16_k(const float* __restrict__ src, hf* __restrict__ dst)
{
    int i = blockIdx.x * blockDim.x + threadIdx.x;
    if (i < BD) dst[i] = __float2half_rn(src[i & 511]);
}

// softmax over KB + weighted read of knowledge (fp16 knowledge)
__global__ void read_k(const float* __restrict__ s4,
                       const hf* __restrict__ kn,
                       float* __restrict__ readv)
{
    int b = blockIdx.x;
    int tid = threadIdx.x;              // 256
    int wid = tid >> 5, lane = tid & 31;
    __shared__ float sv[KBsz];
    __shared__ float wred[8];

    float x = -1e30f;
    if (tid < KBsz) {
        size_t base = (size_t)b * KBsz + tid;
        x = s4[base] + s4[(size_t)MKB + base]
          + s4[2*(size_t)MKB + base] + s4[3*(size_t)MKB + base];
    }
    float m = x;
    #pragma unroll
    for (int o = 16; o; o >>= 1) m = fmaxf(m, __shfl_xor_sync(0xffffffffu, m, o));
    if (lane == 0) wred[wid] = m;
    __syncthreads();
    if (tid == 0) {
        float mm = wred[0];
        #pragma unroll
        for (int w = 1; w < 8; w++) mm = fmaxf(mm, wred[w]);
        wred[0] = mm;
    }
    __syncthreads();
    float mx = wred[0];
    float e = (tid < KBsz) ? expf(x - mx) : 0.f;
    float s = e;
    #pragma unroll
    for (int o = 16; o; o >>= 1) s += __shfl_xor_sync(0xffffffffu, s, o);
    __syncthreads();
    if (lane == 0) wred[wid] = s;
    __syncthreads();
    if (tid == 0) {
        float ss = 0.f;
        #pragma unroll
        for (int w = 0; w < 8; w++) ss += wred[w];
        wred[0] = 1.f / ss;
    }
    __syncthreads();
    if (tid < KBsz) sv[tid] = e * wred[0];
    __syncthreads();

    if (tid < 128) {
        float4 acc = make_float4(0.f, 0.f, 0.f, 0.f);
        const hf* kb = kn + (size_t)b * KBsz * Dd + 4 * tid;
        for (int k = 0; k < KBsz; k++) {
            float w = sv[k];
            uint2 v = *(const uint2*)(kb + (size_t)k * Dd);
            __half2 p0 = *(__half2*)&v.x;
            __half2 p1 = *(__half2*)&v.y;
            acc.x += w * __half2float(__low2half(p0));
            acc.y += w * __half2float(__high2half(p0));
            acc.z += w * __half2float(__low2half(p1));
            acc.w += w * __half2float(__high2half(p1));
        }
        ((float4*)(readv + (size_t)b * Dd))[tid] = acc;
    }
}

__global__ void out_k(const float* __restrict__ mem,
                      const float* __restrict__ att,
                      float* __restrict__ out, int out_size)
{
    int i = blockIdx.x * blockDim.x + threadIdx.x;
    if (i >= BD) return;
    if (i < out_size) out[i] = mem[i];
    if (out_size >= 2 * BD) {
        int b = i >> 9, d = i & 511;
        out[BD + i] = att[((size_t)b * Ss + (Ss - 1)) * Dd + d];
    }
}

// ---------------- launch -----------------------------------------------------
static float* symf(const void* s) { void* p = nullptr; cudaGetSymbolAddress(&p, s); return (float*)p; }
static hf*    symh(const void* s) { void* p = nullptr; cudaGetSymbolAddress(&p, s); return (hf*)p; }
static int*   symi(const void* s) { void* p = nullptr; cudaGetSymbolAddress(&p, s); return (int*)p; }

extern "C" void kernel_launch(void* const* d_in, const int* in_sizes, int n_in,
                              void* d_out, int out_size)
{
    const float* qword     = (const float*)d_in[0];
    const float* qemb      = (const float*)d_in[1];
    const float* knowledge = (const float*)d_in[2];
    const float* ci_w     = (const float*)d_in[4];
    const float* ci_b     = (const float*)d_in[5];
    const float* ciu_w    = (const float*)d_in[6];
    const float* ciu_b    = (const float*)d_in[7];
    const float* ca_w     = (const float*)d_in[8];
    const float* kproj_w  = (const float*)d_in[10];
    const float* kproj_b  = (const float*)d_in[11];
    const float* mproj_w  = (const float*)d_in[12];
    const float* mproj_b  = (const float*)d_in[13];
    const float* concat_w = (const float*)d_in[14];
    const float* concat_b = (const float*)d_in[15];
    const float* concat2_w= (const float*)d_in[16];
    const float* concat2_b= (const float*)d_in[17];
    const float* rattn_w  = (const float*)d_in[18];
    const float* write_w  = (const float*)d_in[20];
    const float* write_b  = (const float*)d_in[21];
    const float* init_mem = (const float*)d_in[22];
    const float* kq_w     = (const float*)d_in[23];
    const float* kq_b     = (const float*)d_in[24];
    const float* val_w    = (const float*)d_in[25];
    const float* val_b    = (const float*)d_in[26];
    float* out = (float*)d_out;

    float* q0     = symf(g_q0);
    float* qall   = symf(g_qall);
    float* ch     = symf(g_ch);
    float* chkv   = symf(g_chkv);
    float* chkey  = chkv;
    float* chval  = chkv + (size_t)Bsz * Ss * Dd;
    float* normed = symf(g_normed);
    float* Amat   = symf(g_Amat);
    float* att    = symf(g_att);
    hf*    kp     = symh(g_kp);
    hf*    kp2    = symh(g_kp2);
    hf*    e1     = symh(g_e1);
    hf*    kn     = symh(g_kn);
    hf*    wb     = symh(g_wb);
    hf*    mp16   = symh(g_mp16);
    float* s4     = symf(g_s4);
    float* readv  = symf(g_read);
    float* Wcat   = symf(g_Wcat);
    float* biascat= symf(g_biascat);
    float* Wkv    = symf(g_Wkv);
    float* bkv    = symf(g_bkv);
    float* zerov  = symf(g_zero);
    float* tmp512 = symf(g_tmp512);
    float* zbuf   = symf(g_zbuf);
    int*   flags  = symi(g_flags);

    static bool init_done = false;
    static cudaStream_t s2 = nullptr;
    static cudaEvent_t evFork = nullptr, evJoin = nullptr;
    if (!init_done) {
        cudaFuncSetAttribute(tgemm_k, cudaFuncAttributeMaxDynamicSharedMemorySize, TG_SMEM);
        cudaFuncSetAttribute(tg23_k,  cudaFuncAttributeMaxDynamicSharedMemorySize, TG_SMEM);
        cudaStreamCreateWithFlags(&s2, cudaStreamNonBlocking);
        cudaEventCreateWithFlags(&evFork, cudaEventDisableTiming);
        cudaEventCreateWithFlags(&evJoin, cudaEventDisableTiming);
        init_done = true;
    }

    auto Gs = [](int M, int N, int Z) { return dim3(N / SBN, M / SBM, Z); };
    const dim3 GT(Dd / 128, NMB);
    hf* NPH = nullptr;

    // kv weight/bias packing on default stream
    copyf_k<<<(Dd*Dd / 4 + 255) / 256, 256>>>(kq_w,  Wkv, Dd*Dd);
    copyf_k<<<(Dd*Dd / 4 + 255) / 256, 256>>>(val_w, Wkv + (size_t)Dd*Dd, Dd*Dd);
    copyf_k<<<(Dd / 4 + 255) / 256, 256>>>(kq_b,  bkv, Dd);
    copyf_k<<<(Dd / 4 + 255) / 256, 256>>>(val_b, bkv + Dd, Dd);

    // ---- fork ----
    cudaEventRecord(evFork, 0);
    cudaStreamWaitEvent(s2, evFork, 0);

    {   // stream s2: conversions + kp + kp2 + write/mproj fusion prep + init state
        size_t nk = (size_t)MKB * Dd;
        cvt16_k<<<(unsigned)((nk / 4 + 255) / 256), 256, 0, s2>>>(knowledge, kn, nk);
        size_t nw = (size_t)Dd * Dd;
        cvt16_k<<<(unsigned)((nw / 4 + 255) / 256), 256, 0, s2>>>(kproj_w,  wb + 0*Dd*Dd, nw);
        cvt16_k<<<(unsigned)((2*nw / 4 + 255) / 256), 256, 0, s2>>>(concat_w, wb + 1*Dd*Dd, 2*nw);
        cvt16_k<<<(unsigned)((nw / 4 + 255) / 256), 256, 0, s2>>>(concat2_w, wb + 3*Dd*Dd, nw);
        // kp / kp2
        tgemm_k<<<GT, 256, TG_SMEM, s2>>>(kn, wb + 0*Dd*Dd, kproj_b, kp);
        tgemm_k<<<GT, 256, TG_SMEM, s2>>>(kp, wb + 2*Dd*Dd, concat_b, kp2);
        // W2 = write_w @ mproj_w into Wcat[1]; Wcat[0] = write_w
        sgemm_k<0><<<Gs(2*Dd, Dd, 1), 256, 0, s2>>>(write_w, Dd, write_w, Dd, Dd,
                                                    mproj_w, zerov, Wcat + (size_t)2*Dd*Dd,
                                                    2*Dd, Dd, Dd, 0, 0, 0, 0, NPH);
        copyf_k<<<(2*Dd*Dd / 4 + 255) / 256, 256, 0, s2>>>(write_w, Wcat, 2*Dd*Dd);
        copyf_k<<<(Dd / 4 + 255) / 256, 256, 0, s2>>>(write_b, biascat, Dd);
        vecmat_k<<<2, 256, 0, s2>>>(write_b, mproj_w, mproj_b, biascat + Dd);   // bias2
        bcast_k<<<(BD + 255) / 256, 256, 0, s2>>>(init_mem, zbuf);              // memory0
        vecmat_k<<<2, 256, 0, s2>>>(init_mem, mproj_w, mproj_b, tmp512);        // mp0 row
        bcast_k<<<(BD + 255) / 256, 256, 0, s2>>>(tmp512, zbuf + BD);           // mp0 fp32
        bcast16_k<<<(BD + 255) / 256, 256, 0, s2>>>(tmp512, mp16);              // mp0 fp16
    }
    cudaEventRecord(evJoin, s2);

    // default stream: question path
    sgemm_k<1><<<Gs(Bsz, Dd, 1), 256>>>(qemb, Dd, qemb, Dd, Dd, ci_w, ci_b, q0,
                                        Bsz, Dd, Dd, 0, 0, 0, 0, NPH);
    sgemm_k<0><<<Gs(Bsz, Dd, Ss), 256>>>(q0, Dd, q0, Dd, Dd, ciu_w, ciu_b, qall,
                                         Bsz, Dd, Dd,
                                         0, (size_t)Dd * Dd, Dd, (size_t)BD, NPH);
    word_attn_k<<<dim3(Bsz, Ss), 256>>>(qall, qword, ca_w, ch);
    sgemm_k<0><<<Gs(Bsz * Ss, Dd, 2), 256>>>(ch, Dd, ch, Dd, Dd, Wkv, bkv, chkv,
                                             Bsz * Ss, Dd, Dd,
                                             0, (size_t)Dd*Dd, Dd, (size_t)Bsz*Ss*Dd, NPH);
    norm_k<<<(BD + 255) / 256, 256>>>(chkey, normed);
    gram_k<<<dim3(TBsz, TS), 256>>>(normed, Amat);
    attv_k<<<dim3(TBsz, TS), 256>>>(Amat, chval, att);

    cudaStreamWaitEvent(0, evJoin, 0);

    int p = 0;
    for (int i = 0; i < Ss; i++) {
        float* mcur = zbuf + (size_t)p * 2 * BD;
        zerofl_k<<<4, 256>>>(flags);
        // fused: e1 producer slices + score consumer slices in one launch
        tg23_k<<<dim3(8, NMB), 256, TG_SMEM>>>(kp, wb + 1*Dd*Dd, kp2, mp16, e1,
                                               wb + 3*Dd*Dd, concat2_b,
                                               att + (size_t)i * Dd, Ss * Dd,
                                               rattn_w, s4, flags);
        read_k<<<Bsz, 256>>>(s4, kn, readv);
        // z=0: memory' ; z=1: mp' (+ fp16 mirror into mp16)
        sgemm_k<0><<<Gs(Bsz, Dd, 2), 256>>>(mcur, Dd, readv, Dd, Dd,
                                            Wcat, biascat,
                                            zbuf + (size_t)(p ^ 1) * 2 * BD,
                                            Bsz, 2 * Dd, Dd,
                                            0, (size_t)2*Dd*Dd, Dd, (size_t)BD, mp16);
        p ^= 1;
    }

    out_k<<<(BD + 255) / 256, 256>>>(zbuf + (size_t)p * 2 * BD, att, out, out_size);
}

// round 17
// speedup vs baseline: 1.2703x; 1.2703x over previous
#include <cuda_runtime.h>
#include <cuda_fp16.h>
#include <math.h>

// Problem constants
#define Bsz 640
#define Dd 512
#define Ss 4
#define Tt 10
#define TBsz 64
#define Ll 30
#define KBsz 196
#define MKB (Bsz*KBsz)   // 125440
#define TS 40            // T*S
#define BD (Bsz*Dd)

typedef __half hf;

// ---------------- scratch (static device globals; no allocations) ----------
__device__ float g_q0[BD];
__device__ float g_qall[Ss*BD];
__device__ float g_ch[Bsz*Ss*Dd];
__device__ float g_chkv[2][Bsz*Ss*Dd];       // [0]=chkey [1]=chval
__device__ float g_normed[Bsz*Ss*Dd];
__device__ float g_Amat[TBsz*TS*TS];
__device__ float g_att[Bsz*Ss*Dd];
__device__ hf    g_kp [(size_t)MKB*Dd];      // know_proj, fp16
__device__ hf    g_kp2[(size_t)MKB*Dd];      // kp2, fp16
__device__ hf    g_e1 [(size_t)MKB*Dd];      // e1, fp16
__device__ hf    g_kn [(size_t)MKB*Dd];      // knowledge, fp16
__device__ hf    g_wb[4][Dd*Dd];             // weights, fp16
__device__ hf    g_mp16[BD];                 // mp in fp16 (per-iter)
__device__ float g_s4[4*(size_t)MKB];        // score partials per N-slice
__device__ float g_read[BD];
__device__ float g_Wcat[2][2*Dd*Dd];         // [0]=write_w copy, [1]=W2=write_w@mproj_w
__device__ float g_biascat[2][Dd];           // [0]=write_b copy, [1]=bias2
__device__ float g_Wkv[2][Dd*Dd];            // [0]=kq_w [1]=val_w (contiguous)
__device__ float g_bkv[2][Dd];
__device__ float g_zero[Dd];                 // stays zero (.bss)
__device__ float g_tmp512[Dd];
__device__ float g_zbuf[4*BD];               // [p][q][BD]: q=0 memory, q=1 mp

__device__ __forceinline__ float eluf(float x){ return x > 0.f ? x : expm1f(x); }

__device__ __forceinline__ void mma_f16(float* cc, const unsigned* a, const unsigned* b){
    asm("mma.sync.aligned.m16n8k16.row.col.f32.f16.f16.f32 "
        "{%0,%1,%2,%3}, {%4,%5,%6,%7}, {%8,%9}, {%0,%1,%2,%3};"
        : "+f"(cc[0]), "+f"(cc[1]), "+f"(cc[2]), "+f"(cc[3])
        : "r"(a[0]), "r"(a[1]), "r"(a[2]), "r"(a[3]), "r"(b[0]), "r"(b[1]));
}
__device__ __forceinline__ void ldm4(unsigned* r, const hf* p){
    unsigned addr = (unsigned)__cvta_generic_to_shared(p);
    asm volatile("ldmatrix.sync.aligned.m8n8.x4.shared.b16 {%0,%1,%2,%3}, [%4];"
                 : "=r"(r[0]), "=r"(r[1]), "=r"(r[2]), "=r"(r[3]) : "r"(addr));
}
__device__ __forceinline__ void ldm4t(unsigned* r, const hf* p){
    unsigned addr = (unsigned)__cvta_generic_to_shared(p);
    asm volatile("ldmatrix.sync.aligned.m8n8.x4.trans.shared.b16 {%0,%1,%2,%3}, [%4];"
                 : "=r"(r[0]), "=r"(r[1]), "=r"(r[2]), "=r"(r[3]) : "r"(addr));
}
__device__ __forceinline__ void cpa16(void* sdst, const void* gsrc){
    unsigned s = (unsigned)__cvta_generic_to_shared(sdst);
    asm volatile("cp.async.cg.shared.global [%0], [%1], 16;" :: "r"(s), "l"(gsrc));
}
__device__ __forceinline__ void cpa_commit(){ asm volatile("cp.async.commit_group;"); }

// =============  big tensor-core GEMM: fp16 single-pass  ======================
// MODE 2: A = Ag * rsv[b] (fused scale, LDG+STS pipeline);
//         t = elu(acc + add); C = fp16(t)
// MODE 3: svec[slice][m] = sum_n elu((acc+bias[n])*colmul[(m/KB)*cmStride+n])*rvec[n]
// MODE 4: C = fp16(acc + bias)
#define TGK 512
#define TGN 512
#define TBK 32
#define NKIT (TGK/TBK)
#define NSTG 2
#define ALD 40
#define BLD 136
#define A_ST (128*ALD)
#define B_ST (TBK*BLD)

template<int MODE>
__global__ __launch_bounds__(256, 2)
void tgemm_k(const hf* __restrict__ Ag, const hf* __restrict__ Bg,
             const float* __restrict__ bias,
             hf* __restrict__ C,
             const hf* __restrict__ addmat,
             const hf* __restrict__ rsv,
             const float* __restrict__ colmul, int cmStride,
             const float* __restrict__ rvec, float* __restrict__ svec)
{
    extern __shared__ hf smem[];
    hf* Abase = smem;                        // [NSTG][128][ALD]
    hf* Bbase = smem + NSTG*A_ST;            // [NSTG][TBK][BLD]

    const int bm = blockIdx.y * 128;
    const int bn = blockIdx.x * 128;
    const int tid = threadIdx.x;
    const int wid = tid >> 5, lane = tid & 31;
    const int warp_m = wid & 1;
    const int warp_n = wid >> 1;
    const int r = lane >> 2, c = lane & 3;
    const int lrow = lane & 15, lcol = (lane >> 4) * 8;

    float acc[4][4][4];
    #pragma unroll
    for (int i = 0; i < 4; i++)
        #pragma unroll
        for (int j = 0; j < 4; j++)
            #pragma unroll
            for (int q = 0; q < 4; q++) acc[i][j][q] = 0.f;

    auto cpA = [&](int k0, int st){
        hf* As = Abase + st * A_ST;
        #pragma unroll
        for (int e2 = 0; e2 < 2; e2++) {
            int e   = tid * 2 + e2;
            int row = e >> 2;
            int seg = (e & 3) * 8;
            cpa16(As + row * ALD + seg,
                  Ag + (size_t)(bm + row) * TGK + k0 * TBK + seg);
        }
    };
    auto cpB = [&](int k0, int st){
        hf* Bs = Bbase + st * B_ST;
        #pragma unroll
        for (int e2 = 0; e2 < 2; e2++) {
            int e   = tid * 2 + e2;
            int row = e >> 4;
            int seg = (e & 15) * 8;
            cpa16(Bs + row * BLD + seg,
                  Bg + (size_t)(k0 * TBK + row) * TGN + bn + seg);
        }
        cpa_commit();
    };

    uint4 ka[2], ra[2];
    auto ldgA = [&](int kt){
        #pragma unroll
        for (int e2 = 0; e2 < 2; e2++) {
            int e   = tid * 2 + e2;
            int row = e >> 2;
            int seg = (e & 3) * 8;
            int m   = bm + row;
            int b   = m / KBsz;
            ka[e2] = *(const uint4*)(Ag  + (size_t)m * TGK + kt * TBK + seg);
            ra[e2] = *(const uint4*)(rsv + (size_t)b * TGK + kt * TBK + seg);
        }
    };
    auto stsA = [&](int st){
        hf* As = Abase + st * A_ST;
        #pragma unroll
        for (int e2 = 0; e2 < 2; e2++) {
            int e   = tid * 2 + e2;
            int row = e >> 2;
            int seg = (e & 3) * 8;
            const __half2* kk = (const __half2*)&ka[e2];
            const __half2* rr2 = (const __half2*)&ra[e2];
            uint4 outv;
            __half2* po = (__half2*)&outv;
            #pragma unroll
            for (int q = 0; q < 4; q++) po[q] = __hmul2(kk[q], rr2[q]);
            *(uint4*)(As + row * ALD + seg) = outv;
        }
    };

    if (MODE == 2) {
        ldgA(0); stsA(0); cpB(0, 0); ldgA(1);
    } else {
        cpA(0, 0); cpB(0, 0);
    }

    for (int k0 = 0; k0 < NKIT; k0++) {
        int st = k0 & 1;
        asm volatile("cp.async.wait_group 0;" ::: "memory");
        __syncthreads();
        if (MODE == 2) {
            if (k0 + 1 < NKIT) { stsA(st ^ 1); cpB(k0 + 1, st ^ 1); }
            if (k0 + 2 < NKIT) ldgA(k0 + 2);
        } else {
            if (k0 + 1 < NKIT) { cpA(k0 + 1, st ^ 1); cpB(k0 + 1, st ^ 1); }
        }

        const hf* Ash = Abase + st * A_ST;
        const hf* Bsh = Bbase + st * B_ST;

        #pragma unroll
        for (int ks = 0; ks < 2; ks++) {
            unsigned ah[4][4], bh[4][2];
            int rr = ks * 16 + lrow;
            int cbase = warp_n * 32 + lcol;
            #pragma unroll
            for (int mt = 0; mt < 4; mt++) {
                int row = warp_m * 64 + mt * 16 + lrow;
                ldm4(ah[mt], Ash + row * ALD + ks * 16 + lcol);
            }
            #pragma unroll
            for (int p = 0; p < 2; p++) {
                unsigned t[4];
                ldm4t(t, Bsh + rr * BLD + cbase + p * 16);
                bh[2*p][0] = t[0]; bh[2*p][1] = t[1];
                bh[2*p+1][0] = t[2]; bh[2*p+1][1] = t[3];
            }
            #pragma unroll
            for (int mt = 0; mt < 4; mt++)
                #pragma unroll
                for (int nt = 0; nt < 4; nt++)
                    mma_f16(acc[mt][nt], ah[mt], bh[nt]);
        }
    }
    __syncthreads();

    if (MODE == 3) {
        __shared__ float sred[128];
        if (tid < 128) sred[tid] = 0.f;
        __syncthreads();
        #pragma unroll
        for (int mt = 0; mt < 4; mt++) {
            int mloc = warp_m*64 + mt*16 + r;
            int m0 = bm + mloc;
            int b0 = m0 / KBsz;
            int b1 = (m0 + 8) / KBsz;
            float p0 = 0.f, p1 = 0.f;
            #pragma unroll
            for (int nt = 0; nt < 4; nt++) {
                int n0 = bn + warp_n*32 + nt*8 + 2*c;
                float v;
                v = eluf((acc[mt][nt][0] + bias[n0  ]) * colmul[(size_t)b0*cmStride + n0  ]); p0 += v*rvec[n0];
                v = eluf((acc[mt][nt][1] + bias[n0+1]) * colmul[(size_t)b0*cmStride + n0+1]); p0 += v*rvec[n0+1];
                v = eluf((acc[mt][nt][2] + bias[n0  ]) * colmul[(size_t)b1*cmStride + n0  ]); p1 += v*rvec[n0];
                v = eluf((acc[mt][nt][3] + bias[n0+1]) * colmul[(size_t)b1*cmStride + n0+1]); p1 += v*rvec[n0+1];
            }
            p0 += __shfl_xor_sync(0xffffffffu, p0, 1);
            p0 += __shfl_xor_sync(0xffffffffu, p0, 2);
            p1 += __shfl_xor_sync(0xffffffffu, p1, 1);
            p1 += __shfl_xor_sync(0xffffffffu, p1, 2);
            if (c == 0) { atomicAdd(&sred[mloc], p0); atomicAdd(&sred[mloc + 8], p1); }
        }
        __syncthreads();
        if (tid < 128)
            svec[(size_t)blockIdx.x * MKB + bm + tid] = sred[tid];
        return;
    }

    #pragma unroll
    for (int mt = 0; mt < 4; mt++) {
        int m0 = bm + warp_m*64 + mt*16 + r;
        #pragma unroll
        for (int nt = 0; nt < 4; nt++) {
            int n0 = bn + warp_n*32 + nt*8 + 2*c;
            #pragma unroll
            for (int half = 0; half < 2; half++) {
                int mm = m0 + half*8;
                float vx = acc[mt][nt][2*half], vy = acc[mt][nt][2*half+1];
                size_t gm = (size_t)mm*TGN + n0;
                if (MODE == 2) {
                    __half2 ad = *(const __half2*)(addmat + gm);
                    vx = eluf(vx + __half2float(__low2half(ad)));
                    vy = eluf(vy + __half2float(__high2half(ad)));
                } else { // MODE 4
                    vx += bias[n0]; vy += bias[n0+1];
                }
                *(__half2*)(C + gm) =
                    __halves2half2(__float2half_rn(vx), __float2half_rn(vy));
            }
        }
    }
}

// ---------------- split / helper kernels -------------------------------------
__global__ void cvt16_k(const float* __restrict__ src, hf* __restrict__ dst, size_t n)
{
    size_t i = ((size_t)blockIdx.x * blockDim.x + threadIdx.x) * 4;
    if (i >= n) return;
    float4 v = *(const float4*)(src + i);
    *(__half2*)(dst + i)     = __halves2half2(__float2half_rn(v.x), __float2half_rn(v.y));
    *(__half2*)(dst + i + 2) = __halves2half2(__float2half_rn(v.z), __float2half_rn(v.w));
}

__global__ void vecmat_k(const float* __restrict__ vec,
                         const float* __restrict__ W,
                         const float* __restrict__ b,
                         float* __restrict__ r)
{
    int n = blockIdx.x * blockDim.x + threadIdx.x;
    if (n >= Dd) return;
    float a = b[n];
    for (int k = 0; k < Dd; k++) a += vec[k] * W[(size_t)k * Dd + n];
    r[n] = a;
}

__global__ void copyf_k(const float* __restrict__ src, float* __restrict__ dst, int n)
{
    int i = (blockIdx.x * blockDim.x + threadIdx.x) * 4;
    if (i < n) *(float4*)(dst + i) = *(const float4*)(src + i);
}

// =====================  small FFMA2 GEMM (64x128 tile)  ======================
__device__ __forceinline__ unsigned long long pack2(float lo, float hi) {
    unsigned long long r;
    asm("mov.b64 %0, {%1, %2};" : "=l"(r) : "f"(lo), "f"(hi));
    return r;
}
__device__ __forceinline__ void unpack2(unsigned long long v, float& lo, float& hi) {
    asm("mov.b64 {%0, %1}, %2;" : "=f"(lo), "=f"(hi) : "l"(v));
}
__device__ __forceinline__ void fma2(unsigned long long& d,
                                     unsigned long long a, unsigned long long b) {
    asm("fma.rn.f32x2 %0, %1, %2, %0;" : "+l"(d) : "l"(a), "l"(b));
}

#define SBM 64
#define SBN 128
#define BKK 16

// z-batched; optional fp16 mirror of the z==1 slab (C16 != nullptr)
template<int MODE>
__global__ __launch_bounds__(256)
void sgemm_k(const float* __restrict__ A, int lda,
             const float* __restrict__ A2, int lda2, int splitK,
             const float* __restrict__ W,
             const float* __restrict__ bias,
             float* __restrict__ C,
             int M, int K, int N,
             size_t strideA, size_t strideW, size_t strideBias, size_t strideC,
             hf* __restrict__ C16)
{
    A    += (size_t)blockIdx.z * strideA;
    A2   += (size_t)blockIdx.z * strideA;
    W    += (size_t)blockIdx.z * strideW;
    bias += (size_t)blockIdx.z * strideBias;
    C    += (size_t)blockIdx.z * strideC;

    __shared__ float As[BKK][SBM];
    __shared__ float Bs[BKK][SBN];

    const int bm = blockIdx.y * SBM;
    const int bn = blockIdx.x * SBN;
    const int tid = threadIdx.x;
    const int ty = tid >> 5;
    const int tx = tid & 31;

    unsigned long long acc2[8][2];
    #pragma unroll
    for (int i = 0; i < 8; i++) { acc2[i][0] = 0ull; acc2[i][1] = 0ull; }

    for (int k0 = 0; k0 < K; k0 += BKK) {
        {
            int e   = tid;
            int row = e >> 2;
            int kq  = (e & 3) * 4;
            int m   = bm + row;
            int k   = k0 + kq;
            const float* src = (k < splitK)
                ? (A  + (size_t)m * lda  + k)
                : (A2 + (size_t)m * lda2 + (k - splitK));
            float4 v = *(const float4*)src;
            As[kq + 0][row] = v.x; As[kq + 1][row] = v.y;
            As[kq + 2][row] = v.z; As[kq + 3][row] = v.w;
        }
        #pragma unroll
        for (int e2 = 0; e2 < 2; e2++) {
            int e   = tid * 2 + e2;
            int row = e >> 5;
            int cc  = (e & 31) * 4;
            float4 v = *(const float4*)(W + (size_t)(k0 + row) * N + bn + cc);
            *(float4*)&Bs[row][cc] = v;
        }
        __syncthreads();
        #pragma unroll
        for (int kk = 0; kk < BKK; kk++) {
            float a[8];
            unsigned long long b2[2];
            #pragma unroll
            for (int i = 0; i < 8; i++) a[i] = As[kk][ty * 8 + i];
            b2[0] = *(const unsigned long long*)&Bs[kk][tx * 4];
            b2[1] = *(const unsigned long long*)&Bs[kk][tx * 4 + 2];
            #pragma unroll
            for (int i = 0; i < 8; i++) {
                unsigned long long pa = pack2(a[i], a[i]);
                fma2(acc2[i][0], pa, b2[0]);
                fma2(acc2[i][1], pa, b2[1]);
            }
        }
        __syncthreads();
    }

    #pragma unroll
    for (int i = 0; i < 8; i++) {
        int m = bm + ty * 8 + i;
        int n = bn + tx * 4;
        float4 v;
        unpack2(acc2[i][0], v.x, v.y);
        unpack2(acc2[i][1], v.z, v.w);
        v.x += bias[n]; v.y += bias[n+1]; v.z += bias[n+2]; v.w += bias[n+3];
        if (MODE == 1) { v.x = tanhf(v.x); v.y = tanhf(v.y); v.z = tanhf(v.z); v.w = tanhf(v.w); }
        *(float4*)(C + (size_t)m * N + n) = v;
        if (C16 != nullptr && blockIdx.z == 1) {
            *(__half2*)(C16 + (size_t)m * N + n) =
                __halves2half2(__float2half_rn(v.x), __float2half_rn(v.y));
            *(__half2*)(C16 + (size_t)m * N + n + 2) =
                __halves2half2(__float2half_rn(v.z), __float2half_rn(v.w));
        }
    }
}

// ---------------- attention / misc kernels (validated) -----------------------
__global__ void word_attn_k(const float* __restrict__ qall,
                            const float* __restrict__ qword,
                            const float* __restrict__ caw,
                            float* __restrict__ ch)
{
    int b = blockIdx.x, s = blockIdx.y;
    __shared__ float qs[Dd];
    __shared__ float lg[Ll];
    int tid = threadIdx.x;
    for (int d = tid; d < Dd; d += 256)
        qs[d] = qall[((size_t)s * Bsz + b) * Dd + d] * caw[d];
    __syncthreads();
    int wid = tid >> 5, lane = tid & 31;
    for (int l = wid; l < Ll; l += 8) {
        const float* qw = qword + ((size_t)b * Ll + l) * Dd;
        float a = 0.f;
        for (int d = lane; d < Dd; d += 32) a += qs[d] * qw[d];
        #pragma unroll
        for (int o = 16; o; o >>= 1) a += __shfl_xor_sync(0xffffffffu, a, o);
        if (lane == 0) lg[l] = a;
    }
    __syncthreads();
    if (tid == 0) {
        float mx = -INFINITY;
        for (int l = 0; l < Ll; l++) mx = fmaxf(mx, lg[l]);
        float sm = 0.f;
        for (int l = 0; l < Ll; l++) { float e = expf(lg[l] - mx); lg[l] = e; sm += e; }
        float inv = 1.f / sm;
        for (int l = 0; l < Ll; l++) lg[l] *= inv;
    }
    __syncthreads();
    for (int d = tid; d < Dd; d += 256) {
        float a = 0.f;
        for (int l = 0; l < Ll; l++) a += lg[l] * qword[((size_t)b * Ll + l) * Dd + d];
        ch[((size_t)b * Ss + s) * Dd + d] = a;
    }
}

__global__ void norm_k(const float* __restrict__ chkey, float* __restrict__ normed)
{
    int i = blockIdx.x * blockDim.x + threadIdx.x;
    if (i >= BD) return;
    int b = i >> 9, d = i & 511;
    size_t base = (size_t)b * Ss * Dd + d;
    float ss = 0.f;
    #pragma unroll
    for (int s = 0; s < Ss; s++) { float v = chkey[base + s * Dd]; ss += v * v; }
    float inv = 1.f / sqrtf(ss);
    #pragma unroll
    for (int s = 0; s < Ss; s++) normed[base + s * Dd] = chkey[base + s * Dd] * inv;
}

__global__ void gram_k(const float* __restrict__ normed, float* __restrict__ Amat)
{
    int tb = blockIdx.x, i = blockIdx.y;
    __shared__ float Ki[Dd];
    __shared__ float lg[TS];
    int tid = threadIdx.x;
    int ti = i / Ss, si = i % Ss;
    size_t rowi = ((size_t)(ti * TBsz + tb) * Ss + si) * Dd;
    for (int d = tid; d < Dd; d += 256) Ki[d] = normed[rowi + d];
    __syncthreads();
    int wid = tid >> 5, lane = tid & 31;
    for (int j = wid; j < TS; j += 8) {
        float a;
        if (j > i) a = -1e30f;
        else {
            int tj = j / Ss, sj = j % Ss;
            size_t rowj = ((size_t)(tj * TBsz + tb) * Ss + sj) * Dd;
            a = 0.f;
            for (int d = lane; d < Dd; d += 32) a += Ki[d] * normed[rowj + d];
            #pragma unroll
            for (int o = 16; o; o >>= 1) a += __shfl_xor_sync(0xffffffffu, a, o);
        }
        if (lane == 0) lg[j] = a;
    }
    __syncthreads();
    if (tid == 0) {
        float mx = -INFINITY;
        for (int j = 0; j < TS; j++) mx = fmaxf(mx, lg[j]);
        float sm = 0.f;
        for (int j = 0; j < TS; j++) { float e = expf(lg[j] - mx); lg[j] = e; sm += e; }
        float inv = 1.f / sm;
        for (int j = 0; j < TS; j++) lg[j] *= inv;
    }
    __syncthreads();
    if (tid < TS) Amat[((size_t)tb * TS + i) * TS + tid] = lg[tid];
}

__global__ void attv_k(const float* __restrict__ Amat,
                       const float* __restrict__ chval,
                       float* __restrict__ att)
{
    int tb = blockIdx.x, i = blockIdx.y;
    __shared__ float aw[TS];
    int tid = threadIdx.x;
    if (tid < TS) aw[tid] = Amat[((size_t)tb * TS + i) * TS + tid];
    __syncthreads();
    int ti = i / Ss, si = i % Ss;
    for (int d = tid; d < Dd; d += 256) {
        float a = 0.f;
        for (int j = 0; j <= i; j++) {
            int tj = j / Ss, sj = j % Ss;
            a += aw[j] * chval[((size_t)(tj * TBsz + tb) * Ss + sj) * Dd + d];
        }
        att[((size_t)(ti * TBsz + tb) * Ss + si) * Dd + d] = a;
    }
}

__global__ void bcast_k(const float* __restrict__ src, float* __restrict__ dst)
{
    int i = blockIdx.x * blockDim.x + threadIdx.x;
    if (i < BD) dst[i] = src[i & 511];
}

__global__ void bcast16_k(const float* __restrict__ src, hf* __restrict__ dst)
{
    int i = blockIdx.x * blockDim.x + threadIdx.x;
    if (i < BD) dst[i] = __float2half_rn(src[i & 511]);
}

// softmax over KB (summing 4 N-slice partials, parallel reductions)
// + vectorized weighted read of knowledge (fp32 knowledge — precision-safe)
__global__ void read_k(const float* __restrict__ s4,
                       const float* __restrict__ knowledge,
                       float* __restrict__ readv)
{
    int b = blockIdx.x;
    int tid = threadIdx.x;              // 256
    int wid = tid >> 5, lane = tid & 31;
    __shared__ float sv[KBsz];
    __shared__ float wred[8];

    float x = -1e30f;
    if (tid < KBsz) {
        size_t base = (size_t)b * KBsz + tid;
        x = s4[base] + s4[(size_t)MKB + base]
          + s4[2*(size_t)MKB + base] + s4[3*(size_t)MKB + base];
    }
    float m = x;
    #pragma unroll
    for (int o = 16; o; o >>= 1) m = fmaxf(m, __shfl_xor_sync(0xffffffffu, m, o));
    if (lane == 0) wred[wid] = m;
    __syncthreads();
    if (tid == 0) {
        float mm = wred[0];
        #pragma unroll
        for (int w = 1; w < 8; w++) mm = fmaxf(mm, wred[w]);
        wred[0] = mm;
    }
    __syncthreads();
    float mx = wred[0];
    float e = (tid < KBsz) ? expf(x - mx) : 0.f;
    float s = e;
    #pragma unroll
    for (int o = 16; o; o >>= 1) s += __shfl_xor_sync(0xffffffffu, s, o);
    __syncthreads();
    if (lane == 0) wred[wid] = s;
    __syncthreads();
    if (tid == 0) {
        float ss = 0.f;
        #pragma unroll
        for (int w = 0; w < 8; w++) ss += wred[w];
        wred[0] = 1.f / ss;
    }
    __syncthreads();
    if (tid < KBsz) sv[tid] = e * wred[0];
    __syncthreads();

    if (tid < 128) {
        const float4* kn = (const float4*)(knowledge + (size_t)b * KBsz * Dd);
        float4 acc = make_float4(0.f, 0.f, 0.f, 0.f);
        int k = 0;
        #pragma unroll 4
        for (; k + 4 <= KBsz; k += 4) {
            #pragma unroll
            for (int u = 0; u < 4; u++) {
                float w = sv[k + u];
                float4 t = kn[(size_t)(k + u) * 128 + tid];
                acc.x += w * t.x; acc.y += w * t.y;
                acc.z += w * t.z; acc.w += w * t.w;
            }
        }
        for (; k < KBsz; k++) {
            float w = sv[k];
            float4 t = kn[(size_t)k * 128 + tid];
            acc.x += w * t.x; acc.y += w * t.y;
            acc.z += w * t.z; acc.w += w * t.w;
        }
        ((float4*)(readv + (size_t)b * Dd))[tid] = acc;
    }
}

__global__ void out_k(const float* __restrict__ mem,
                      const float* __restrict__ att,
                      float* __restrict__ out, int out_size)
{
    int i = blockIdx.x * blockDim.x + threadIdx.x;
    if (i >= BD) return;
    if (i < out_size) out[i] = mem[i];
    if (out_size >= 2 * BD) {
        int b = i >> 9, d = i & 511;
        out[BD + i] = att[((size_t)b * Ss + (Ss - 1)) * Dd + d];
    }
}

// ---------------- launch -----------------------------------------------------
static float* symf(const void* s) { void* p = nullptr; cudaGetSymbolAddress(&p, s); return (float*)p; }
static hf*    symh(const void* s) { void* p = nullptr; cudaGetSymbolAddress(&p, s); return (hf*)p; }

#define TG_SMEM (int)((NSTG*A_ST + NSTG*B_ST) * sizeof(hf))

extern "C" void kernel_launch(void* const* d_in, const int* in_sizes, int n_in,
                              void* d_out, int out_size)
{
    const float* qword     = (const float*)d_in[0];
    const float* qemb      = (const float*)d_in[1];
    const float* knowledge = (const float*)d_in[2];
    const float* ci_w     = (const float*)d_in[4];
    const float* ci_b     = (const float*)d_in[5];
    const float* ciu_w    = (const float*)d_in[6];
    const float* ciu_b    = (const float*)d_in[7];
    const float* ca_w     = (const float*)d_in[8];
    const float* kproj_w  = (const float*)d_in[10];
    const float* kproj_b  = (const float*)d_in[11];
    const float* mproj_w  = (const float*)d_in[12];
    const float* mproj_b  = (const float*)d_in[13];
    const float* concat_w = (const float*)d_in[14];
    const float* concat_b = (const float*)d_in[15];
    const float* concat2_w= (const float*)d_in[16];
    const float* concat2_b= (const float*)d_in[17];
    const float* rattn_w  = (const float*)d_in[18];
    const float* write_w  = (const float*)d_in[20];
    const float* write_b  = (const float*)d_in[21];
    const float* init_mem = (const float*)d_in[22];
    const float* kq_w     = (const float*)d_in[23];
    const float* kq_b     = (const float*)d_in[24];
    const float* val_w    = (const float*)d_in[25];
    const float* val_b    = (const float*)d_in[26];
    float* out = (float*)d_out;

    float* q0     = symf(g_q0);
    float* qall   = symf(g_qall);
    float* ch     = symf(g_ch);
    float* chkv   = symf(g_chkv);
    float* chkey  = chkv;
    float* chval  = chkv + (size_t)Bsz * Ss * Dd;
    float* normed = symf(g_normed);
    float* Amat   = symf(g_Amat);
    float* att    = symf(g_att);
    hf*    kp     = symh(g_kp);
    hf*    kp2    = symh(g_kp2);
    hf*    e1     = symh(g_e1);
    hf*    kn     = symh(g_kn);
    hf*    wb     = symh(g_wb);
    hf*    mp16   = symh(g_mp16);
    float* s4     = symf(g_s4);
    float* readv  = symf(g_read);
    float* Wcat   = symf(g_Wcat);
    float* biascat= symf(g_biascat);
    float* Wkv    = symf(g_Wkv);
    float* bkv    = symf(g_bkv);
    float* zerov  = symf(g_zero);
    float* tmp512 = symf(g_tmp512);
    float* zbuf   = symf(g_zbuf);

    static bool init_done = false;
    static cudaStream_t s2 = nullptr;
    static cudaEvent_t evFork = nullptr, evJoin = nullptr;
    if (!init_done) {
        cudaFuncSetAttribute(tgemm_k<2>, cudaFuncAttributeMaxDynamicSharedMemorySize, TG_SMEM);
        cudaFuncSetAttribute(tgemm_k<3>, cudaFuncAttributeMaxDynamicSharedMemorySize, TG_SMEM);
        cudaFuncSetAttribute(tgemm_k<4>, cudaFuncAttributeMaxDynamicSharedMemorySize, TG_SMEM);
        cudaStreamCreateWithFlags(&s2, cudaStreamNonBlocking);
        cudaEventCreateWithFlags(&evFork, cudaEventDisableTiming);
        cudaEventCreateWithFlags(&evJoin, cudaEventDisableTiming);
        init_done = true;
    }

    auto Gs = [](int M, int N, int Z) { return dim3(N / SBN, M / SBM, Z); };
    const dim3 GT(Dd / 128, MKB / 128);
    const float* NPF = nullptr;
    hf* NPH = nullptr;

    // kv weight/bias packing on default stream
    copyf_k<<<(Dd*Dd / 4 + 255) / 256, 256>>>(kq_w,  Wkv, Dd*Dd);
    copyf_k<<<(Dd*Dd / 4 + 255) / 256, 256>>>(val_w, Wkv + (size_t)Dd*Dd, Dd*Dd);
    copyf_k<<<(Dd / 4 + 255) / 256, 256>>>(kq_b,  bkv, Dd);
    copyf_k<<<(Dd / 4 + 255) / 256, 256>>>(val_b, bkv + Dd, Dd);

    // ---- fork ----
    cudaEventRecord(evFork, 0);
    cudaStreamWaitEvent(s2, evFork, 0);

    {   // stream s2: conversions + kp + kp2 + write/mproj fusion prep + init state
        size_t nk = (size_t)MKB * Dd;
        cvt16_k<<<(unsigned)((nk / 4 + 255) / 256), 256, 0, s2>>>(knowledge, kn, nk);
        size_t nw = (size_t)Dd * Dd;
        cvt16_k<<<(unsigned)((nw / 4 + 255) / 256), 256, 0, s2>>>(kproj_w,  wb + 0*Dd*Dd, nw);
        cvt16_k<<<(unsigned)((2*nw / 4 + 255) / 256), 256, 0, s2>>>(concat_w, wb + 1*Dd*Dd, 2*nw);
        cvt16_k<<<(unsigned)((nw / 4 + 255) / 256), 256, 0, s2>>>(concat2_w, wb + 3*Dd*Dd, nw);
        // kp / kp2 (fp16 outputs)
        tgemm_k<4><<<GT, 256, TG_SMEM, s2>>>(kn, wb + 0*Dd*Dd,
                                             kproj_b, kp, NPH, NPH, NPF, 0, NPF, nullptr);
        tgemm_k<4><<<GT, 256, TG_SMEM, s2>>>(kp, wb + 2*Dd*Dd,
                                             concat_b, kp2, NPH, NPH, NPF, 0, NPF, nullptr);
        // W2 = write_w @ mproj_w into Wcat[1]; Wcat[0] = write_w
        sgemm_k<0><<<Gs(2*Dd, Dd, 1), 256, 0, s2>>>(write_w, Dd, write_w, Dd, Dd,
                                                    mproj_w, zerov, Wcat + (size_t)2*Dd*Dd,
                                                    2*Dd, Dd, Dd, 0, 0, 0, 0, NPH);
        copyf_k<<<(2*Dd*Dd / 4 + 255) / 256, 256, 0, s2>>>(write_w, Wcat, 2*Dd*Dd);
        copyf_k<<<(Dd / 4 + 255) / 256, 256, 0, s2>>>(write_b, biascat, Dd);
        vecmat_k<<<2, 256, 0, s2>>>(write_b, mproj_w, mproj_b, biascat + Dd);   // bias2
        bcast_k<<<(BD + 255) / 256, 256, 0, s2>>>(init_mem, zbuf);              // memory0
        vecmat_k<<<2, 256, 0, s2>>>(init_mem, mproj_w, mproj_b, tmp512);        // mp0 row
        bcast_k<<<(BD + 255) / 256, 256, 0, s2>>>(tmp512, zbuf + BD);           // mp0 fp32
        bcast16_k<<<(BD + 255) / 256, 256, 0, s2>>>(tmp512, mp16);              // mp0 fp16
    }
    cudaEventRecord(evJoin, s2);

    // default stream: question path
    sgemm_k<1><<<Gs(Bsz, Dd, 1), 256>>>(qemb, Dd, qemb, Dd, Dd, ci_w, ci_b, q0,
                                        Bsz, Dd, Dd, 0, 0, 0, 0, NPH);
    sgemm_k<0><<<Gs(Bsz, Dd, Ss), 256>>>(q0, Dd, q0, Dd, Dd, ciu_w, ciu_b, qall,
                                         Bsz, Dd, Dd,
                                         0, (size_t)Dd * Dd, Dd, (size_t)BD, NPH);
    word_attn_k<<<dim3(Bsz, Ss), 256>>>(qall, qword, ca_w, ch);
    sgemm_k<0><<<Gs(Bsz * Ss, Dd, 2), 256>>>(ch, Dd, ch, Dd, Dd, Wkv, bkv, chkv,
                                             Bsz * Ss, Dd, Dd,
                                             0, (size_t)Dd*Dd, Dd, (size_t)Bsz*Ss*Dd, NPH);
    norm_k<<<(BD + 255) / 256, 256>>>(chkey, normed);
    gram_k<<<dim3(TBsz, TS), 256>>>(normed, Amat);
    attv_k<<<dim3(TBsz, TS), 256>>>(Amat, chval, att);

    cudaStreamWaitEvent(0, evJoin, 0);

    int p = 0;
    for (int i = 0; i < Ss; i++) {
        float* mcur = zbuf + (size_t)p * 2 * BD;
        // e1 = elu((kp * mp) @ W1 + kp2), scale fused into A load (mp16 ready)
        tgemm_k<2><<<GT, 256, TG_SMEM>>>(kp, wb + 1*Dd*Dd,
                                         NPF, e1, kp2, mp16, NPF, 0, NPF, nullptr);
        tgemm_k<3><<<GT, 256, TG_SMEM>>>(e1, wb + 3*Dd*Dd,
                                         concat2_b, NPH, NPH, NPH,
                                         att + (size_t)i * Dd, Ss * Dd, rattn_w, s4);
        read_k<<<Bsz, 256>>>(s4, knowledge, readv);
        // z=0: memory' ; z=1: mp' (+ fp16 mirror into mp16 for next iter)
        sgemm_k<0><<<Gs(Bsz, Dd, 2), 256>>>(mcur, Dd, readv, Dd, Dd,
                                            Wcat, biascat,
                                            zbuf + (size_t)(p ^ 1) * 2 * BD,
                                            Bsz, 2 * Dd, Dd,
                                            0, (size_t)2*Dd*Dd, Dd, (size_t)BD, mp16);
        p ^= 1;
    }

    out_k<<<(BD + 255) / 256, 256>>>(zbuf + (size_t)p * 2 * BD, att, out, out_size);
}